// round 7
// baseline (speedup 1.0000x reference)
#include <cuda_runtime.h>

// Persistent LSTM: B=128, T=365, D=32, H=512, fp32, out[b,t,:]=h_t.
// 128 CTAs x 512 threads (16 warps, 4/SMSP). CTA tile: 32 batch x 16 units.
// 4-way split-K (k quarters of 136) reduced via 2 smem buffers.
// W resident transposed sWT[gatecol][k] (pitch 548). A transposed sAT[k][m]
// pitch 32 -> h region is one contiguous 64KB block staged per step with a
// single cp.async.bulk from the transposed aux buffer g_hT (mbarrier wait).
// x(t+1) prefetched by warps 4-15 overlapped with warps 0-3's epilogue.
// Lane l: gates {l>>4,(l>>4)+2} of unit l&15; partners fused via shfl.xor(16).

#define B_   128
#define T_   365
#define D_   32
#define H_   512
#define G4   2048
#define KTOT 544
#define KSPL 136
#define NCTA 128
#define NTHR 512
#define WPITCH 548

// smem layout in floats: [mbar 4][W 64*548][A 544*32][red 2*128*10*2]
#define SW_OFF   4
#define SW_FLOATS (64 * WPITCH)            // 35072
#define SA_OFF   (SW_OFF + SW_FLOATS)
#define SA_FLOATS (KTOT * 32)              // 17408
#define RED_OFF  (SA_OFF + SA_FLOATS)
#define RED_PITCH 10                       // u64 per entry (conflict-free)
#define RED_FLOATS (128 * RED_PITCH * 2)   // 2560 per buffer
#define SMEM_BYTES ((RED_OFF + 2 * RED_FLOATS) * 4)   // 230416

__device__ float g_hT[2][4][512][32];   // [parity][m-group][unit][m-local]
__device__ unsigned int g_arrive[4];
__device__ volatile unsigned int g_release[4];

__global__ void init_barrier_kernel() {
    if (threadIdx.x < 4) { g_arrive[threadIdx.x] = 0u; g_release[threadIdx.x] = 0u; }
}

__device__ __forceinline__ unsigned long long pack2(float v) {
    unsigned long long r;
    asm("mov.b64 %0, {%1, %1};" : "=l"(r) : "f"(v));
    return r;
}
__device__ __forceinline__ void ffma2(unsigned long long& d,
                                      unsigned long long a,
                                      unsigned long long b) {
    asm("fma.rn.f32x2 %0, %1, %2, %0;" : "+l"(d) : "l"(a), "l"(b));
}
__device__ __forceinline__ void fadd2(unsigned long long& d, unsigned long long a) {
    asm("add.rn.f32x2 %0, %0, %1;" : "+l"(d) : "l"(a));
}
__device__ __forceinline__ void unpack2(unsigned long long v, float& lo, float& hi) {
    asm("mov.b64 {%0, %1}, %2;" : "=f"(lo), "=f"(hi) : "l"(v));
}
__device__ __forceinline__ float fsig(float z) {
    return 1.0f / (1.0f + __expf(-z));
}
__device__ __forceinline__ float ftanh_(float z) {
    return 1.0f - 2.0f / (__expf(2.0f * z) + 1.0f);
}
__device__ __forceinline__ unsigned int smem_u32(const void* p) {
    return (unsigned int)__cvta_generic_to_shared(p);
}
__device__ __forceinline__ void mbar_init(unsigned int mbar, unsigned int cnt) {
    asm volatile("mbarrier.init.shared.b64 [%0], %1;" :: "r"(mbar), "r"(cnt) : "memory");
}
__device__ __forceinline__ void mbar_expect_tx(unsigned int mbar, unsigned int bytes) {
    asm volatile("mbarrier.arrive.expect_tx.shared.b64 _, [%0], %1;"
                 :: "r"(mbar), "r"(bytes) : "memory");
}
__device__ __forceinline__ void bulk_g2s(unsigned int dst, const void* src,
                                         unsigned int bytes, unsigned int mbar) {
    asm volatile("cp.async.bulk.shared::cluster.global.mbarrier::complete_tx::bytes "
                 "[%0], [%1], %2, [%3];"
                 :: "r"(dst), "l"(src), "r"(bytes), "r"(mbar) : "memory");
}
__device__ __forceinline__ void mbar_wait(unsigned int mbar, unsigned int parity) {
    asm volatile(
        "{\n\t.reg .pred P1;\n\t"
        "WAIT_LOOP_%=:\n\t"
        "mbarrier.try_wait.parity.shared.b64 P1, [%0], %1;\n\t"
        "@P1 bra.uni WAIT_DONE_%=;\n\t"
        "bra.uni WAIT_LOOP_%=;\n\t"
        "WAIT_DONE_%=:\n\t}"
        :: "r"(mbar), "r"(parity) : "memory");
}

__global__ __launch_bounds__(NTHR, 1) void lstm_persistent(
    const float* __restrict__ x,    // [B,T,D]
    const float* __restrict__ Wx,   // [D,4H]
    const float* __restrict__ Wh,   // [H,4H]
    const float* __restrict__ bias, // [4H]
    float* __restrict__ out)        // [B,T,H]
{
    extern __shared__ float smem[];
    float* sWT = smem + SW_OFF;                      // [64][WPITCH]
    float* sAT = smem + SA_OFF;                      // [KTOT][32]
    unsigned long long* buf0 = (unsigned long long*)(smem + RED_OFF);
    unsigned long long* buf1 = buf0 + 128 * RED_PITCH;
    const unsigned int mbar = smem_u32(smem);        // first 8 bytes
    const unsigned int sAT32 = smem_u32(sAT);

    const int tid  = threadIdx.x;
    const int warp = tid >> 5;
    const int lane = tid & 31;
    const int wm   = warp & 3;                 // m-group (rows 8wm..8wm+7)
    const int kh   = warp >> 2;                // k-quarter 0..3
    const int ub   = blockIdx.x & 31;
    const int mb   = blockIdx.x >> 5;
    const int j0   = ub * 16;
    const int m0   = mb * 32;
    const int u    = lane & 15;
    const int gA   = lane >> 4;
    const int j    = j0 + u;

    // ---- prologue ----
    if (tid == 0) mbar_init(mbar, 1);
    for (int i = 0; i < (64 * KTOT) / NTHR; ++i) {   // 68 iters
        int idx = i * NTHR + tid;
        int r = idx & 63;
        int k = idx >> 6;
        int col = (r >> 4) * H_ + j0 + (r & 15);
        float v = (k < H_) ? Wh[(size_t)k * G4 + col]
                           : Wx[(size_t)(k - H_) * G4 + col];
        sWT[r * WPITCH + k] = v;
    }
    const float biasA = bias[gA * H_ + j];
    const float biasB = bias[(gA + 2) * H_ + j];
    float c_reg[8] = {0.f,0.f,0.f,0.f,0.f,0.f,0.f,0.f};

    // zero h region (16384 floats) + stage x(0)
    {
        float4 z4 = make_float4(0.f, 0.f, 0.f, 0.f);
        #pragma unroll
        for (int i = 0; i < 8; ++i)
            *(float4*)(sAT + (i * NTHR + tid) * 4) = z4;
        for (int e = tid; e < 1024; e += NTHR) {
            int d = e >> 5, m = e & 31;
            sAT[(512 + d) * 32 + m] =
                x[(size_t)(m0 + m) * (T_ * D_) + d];
        }
    }
    __syncthreads();

    const float* wrA = sWT + lane * WPITCH + kh * KSPL;
    const float* wrB = wrA + 32 * WPITCH;
    const float* aB  = sAT + kh * KSPL * 32 + wm * 8;
    const int slot = wm * 32 + lane;

    for (int t = 0; t < T_; ++t) {
        if (t > 0) {
            // one bulk copy: g_hT[(t-1)&1][mb] (64KB contiguous) -> sAT
            if (tid == 0) {
                mbar_expect_tx(mbar, 65536u);
                bulk_g2s(sAT32, &g_hT[(t - 1) & 1][mb][0][0], 65536u, mbar);
            }
            mbar_wait(mbar, (unsigned)((t - 1) & 1));
        }

        // ---- k-loop (quarter range): 8 m x 2 gate-cols per lane ----
        unsigned long long acc[4][2] = {};
        #pragma unroll 2
        for (int k4 = 0; k4 < KSPL; k4 += 4) {
            float4 wa = *(const float4*)(wrA + k4);
            float4 wb = *(const float4*)(wrB + k4);
            #pragma unroll
            for (int kk = 0; kk < 4; ++kk) {
                const float* arow = aB + (k4 + kk) * 32;
                ulonglong2 a01 = *(const ulonglong2*)(arow);
                ulonglong2 a23 = *(const ulonglong2*)(arow + 4);
                float wak = (kk == 0) ? wa.x : (kk == 1) ? wa.y
                          : (kk == 2) ? wa.z : wa.w;
                float wbk = (kk == 0) ? wb.x : (kk == 1) ? wb.y
                          : (kk == 2) ? wb.z : wb.w;
                unsigned long long wa2 = pack2(wak);
                unsigned long long wb2 = pack2(wbk);
                ffma2(acc[0][0], a01.x, wa2); ffma2(acc[0][1], a01.x, wb2);
                ffma2(acc[1][0], a01.y, wa2); ffma2(acc[1][1], a01.y, wb2);
                ffma2(acc[2][0], a23.x, wa2); ffma2(acc[2][1], a23.x, wb2);
                ffma2(acc[3][0], a23.y, wa2); ffma2(acc[3][1], a23.y, wb2);
            }
        }

        // ---- split-K reduction (two rounds, two buffers) ----
        if (kh == 1) {
            unsigned long long* d0 = buf0 + (size_t)slot * RED_PITCH;
            #pragma unroll
            for (int p = 0; p < 4; ++p)
                *(ulonglong2*)(d0 + 2 * p) = make_ulonglong2(acc[p][0], acc[p][1]);
        }
        if (kh == 3) {
            unsigned long long* d1 = buf1 + (size_t)slot * RED_PITCH;
            #pragma unroll
            for (int p = 0; p < 4; ++p)
                *(ulonglong2*)(d1 + 2 * p) = make_ulonglong2(acc[p][0], acc[p][1]);
        }
        __syncthreads();
        if (kh == 0) {
            const unsigned long long* s0 = buf0 + (size_t)slot * RED_PITCH;
            #pragma unroll
            for (int p = 0; p < 4; ++p) {
                ulonglong2 v = *(const ulonglong2*)(s0 + 2 * p);
                fadd2(acc[p][0], v.x); fadd2(acc[p][1], v.y);
            }
        }
        if (kh == 2) {
            unsigned long long* s1 = buf1 + (size_t)slot * RED_PITCH;
            #pragma unroll
            for (int p = 0; p < 4; ++p) {
                ulonglong2 v = *(const ulonglong2*)(s1 + 2 * p);
                fadd2(acc[p][0], v.x); fadd2(acc[p][1], v.y);
                *(ulonglong2*)(s1 + 2 * p) = make_ulonglong2(acc[p][0], acc[p][1]);
            }
        }
        __syncthreads();

        // ---- warps 4-15: prefetch x(t+1) while kh0 runs the epilogue ----
        if (kh != 0) {
            if (t + 1 < T_) {
                for (int e = tid - 128; e < 1024; e += 384) {
                    int d = e >> 5, m = e & 31;
                    sAT[(512 + d) * 32 + m] =
                        x[(size_t)(m0 + m) * (T_ * D_) + (size_t)(t + 1) * D_ + d];
                }
            }
        } else {
            const unsigned long long* s1 = buf1 + (size_t)slot * RED_PITCH;
            #pragma unroll
            for (int p = 0; p < 4; ++p) {
                ulonglong2 v = *(const ulonglong2*)(s1 + 2 * p);
                fadd2(acc[p][0], v.x); fadd2(acc[p][1], v.y);
            }

            // epilogue: lanes<16 have (i,g); lanes>=16 have (f,o)
            float zA[8], zB[8];
            #pragma unroll
            for (int p = 0; p < 4; ++p) {
                unpack2(acc[p][0], zA[2 * p], zA[2 * p + 1]);
                unpack2(acc[p][1], zB[2 * p], zB[2 * p + 1]);
            }
            float v[8];
            if (lane < 16) {
                #pragma unroll
                for (int r = 0; r < 8; ++r)
                    v[r] = fsig(zA[r] + biasA) * ftanh_(zB[r] + biasB);
            }
            #pragma unroll
            for (int r = 0; r < 8; ++r)
                v[r] = __shfl_sync(0xffffffffu, v[r], lane ^ 16);
            if (lane >= 16) {
                float h[8];
                #pragma unroll
                for (int r = 0; r < 8; ++r) {
                    float cn = fsig(zA[r] + biasA) * c_reg[r] + v[r];
                    c_reg[r] = cn;
                    h[r] = fsig(zB[r] + biasB) * ftanh_(cn);
                    out[(size_t)(m0 + wm * 8 + r) * ((size_t)T_ * H_) +
                        (size_t)t * H_ + j] = h[r];
                }
                float* hdst = &g_hT[t & 1][mb][j][wm * 8];
                *(float4*)(hdst)     = make_float4(h[0], h[1], h[2], h[3]);
                *(float4*)(hdst + 4) = make_float4(h[4], h[5], h[6], h[7]);
                __threadfence();
            }
        }
        __syncthreads();

        // ---- group barrier (32 CTAs sharing this m-group) ----
        if (tid == 0) {
            unsigned prev = atomicAdd(&g_arrive[mb], 1u);
            if (prev == (unsigned)(t + 1) * 32u - 1u) {
                g_release[mb] = (unsigned)(t + 1);
            } else {
                while (g_release[mb] < (unsigned)(t + 1)) { }
            }
        }
        __syncthreads();
    }
}

extern "C" void kernel_launch(void* const* d_in, const int* in_sizes, int n_in,
                              void* d_out, int out_size) {
    const float* x  = (const float*)d_in[0];
    const float* Wx = (const float*)d_in[1];
    const float* Wh = (const float*)d_in[2];
    const float* b  = (const float*)d_in[3];
    float* out = (float*)d_out;

    static bool attr_set = false;
    if (!attr_set) {
        cudaFuncSetAttribute(lstm_persistent,
                             cudaFuncAttributeMaxDynamicSharedMemorySize,
                             SMEM_BYTES);
        attr_set = true;
    }

    init_barrier_kernel<<<1, 32>>>();
    lstm_persistent<<<NCTA, NTHR, SMEM_BYTES>>>(x, Wx, Wh, b, out);
}